// round 15
// baseline (speedup 1.0000x reference)
#include <cuda_runtime.h>

#define B 256
#define R 1152
#define C 10
#define O 16
#define I 8
#define K9 (R * I)      // 9216
#define N160 (C * O)    // 160
#define NKS 64          // K-split for gemm1
#define KC (K9 / NKS)   // 144
#define ZS 4            // gemm2 batch split

__device__ float g_b[R * C];
__device__ float g_bp[ZS * R * C];       // gemm2 batch-split partials
__device__ float g_c[R * C];
__device__ float g_xT[K9 * B];           // xT[k][b]  (gemm1 only)
__device__ float g_Wt[K9 * N160];        // Wt[k=(r,i)][n=(c,o)] = W[r,c,o,i]
__device__ float g_v[B * N160];          // v[b][n]
__device__ float g_spart[NKS * B * N160];

// Fused prologue: [0,2304) transpose x -> g_xT; [2304,3456) rearrange W -> g_Wt;
// [3456,3501) init g_c = 1/R, g_b = 0.
__global__ void __launch_bounds__(256) prologue_k(const float* __restrict__ x,
                                                  const float* __restrict__ W) {
    __shared__ float sbuf[1280];  // transpose needs 32*33=1056, W tile needs 1280
    const int bid = blockIdx.x;
    const int tid = threadIdx.x;

    if (bid < 2304) {                 // transpose: 288 x 8 tiles of 32x32
        const int k0 = (bid % 288) * 32, b0 = (bid / 288) * 32;
        const int tx = tid & 31, ty = tid >> 5;  // 32 x 8
#pragma unroll
        for (int j = 0; j < 32; j += 8)
            sbuf[(ty + j) * 33 + tx] = x[(size_t)(b0 + ty + j) * K9 + k0 + tx];
        __syncthreads();
#pragma unroll
        for (int j = 0; j < 32; j += 8)
            g_xT[(size_t)(k0 + ty + j) * B + b0 + tx] = sbuf[tx * 33 + ty + j];
    } else if (bid < 3456) {          // W rearrange, one route per block
        const int r = bid - 2304;
        for (int idx = tid; idx < 1280; idx += 256)
            sbuf[idx] = W[(size_t)r * 1280 + idx];   // layout (c,o,i)
        __syncthreads();
        for (int idx = tid; idx < 1280; idx += 256) {
            int i = idx / N160, n = idx - i * N160;  // n = c*16+o
            g_Wt[(size_t)(r * 8 + i) * N160 + n] = sbuf[n * I + i];
        }
    } else {                          // init
        int i = (bid - 3456) * 256 + tid;
        if (i < R * C) { g_c[i] = 1.0f / (float)R; g_b[i] = 0.0f; }
    }
}

// softmax over routes per capsule c; folds in the ZS gemm2 partials and
// updates g_b for the next iteration. One block per c.
__global__ void __launch_bounds__(128) softmax_k() {
    const int c = blockIdx.x;
    const int tid = threadIdx.x;
    __shared__ float bsm[R];
    __shared__ float red[128];

    for (int r = tid; r < R; r += 128) {
        float t = g_b[r * C + c];
#pragma unroll
        for (int z = 0; z < ZS; z++) t += g_bp[z * (R * C) + r * C + c];
        bsm[r] = t;
    }
    __syncthreads();

    float m = -1e30f;
    for (int r = tid; r < R; r += 128) m = fmaxf(m, bsm[r]);
    red[tid] = m;
    __syncthreads();
    for (int s = 64; s > 0; s >>= 1) {
        if (tid < s) red[tid] = fmaxf(red[tid], red[tid + s]);
        __syncthreads();
    }
    m = red[0];
    __syncthreads();

    float sum = 0.0f;
    for (int r = tid; r < R; r += 128) sum += expf(bsm[r] - m);
    red[tid] = sum;
    __syncthreads();
    for (int s = 64; s > 0; s >>= 1) {
        if (tid < s) red[tid] += red[tid + s];
        __syncthreads();
    }
    float inv = 1.0f / red[0];

    for (int r = tid; r < R; r += 128) {
        g_b[r * C + c] = bsm[r];
        g_c[r * C + c] = expf(bsm[r] - m) * inv;
    }
}

// GEMM1 partials: spart[ks][b][n] = sum_{k in chunk} xT[k][b] * (c[r(k),cap(n)] * Wt[k][n])
// tile 128(b) x 32(n), 128 threads, 8x4/thread, single-buffered (R7 structure).
// c_ij scale folded via smem csm (no scattered LDG). grid (2, 5, NKS).
__global__ void __launch_bounds__(128) gemm1_k() {
    const int b0 = blockIdx.x * 128, n0 = blockIdx.y * 32;
    const int k0 = blockIdx.z * KC;
    const int tid = threadIdx.x;
    const int tn = tid & 7, tm = tid >> 3;  // tn 0..7 (n), tm 0..15 (b)

    __shared__ float xs[16][128];
    __shared__ float ws[16][32];
    __shared__ float csm[(KC / 8) * 2];     // 18 routes x 2 caps
    float acc[8][4];
#pragma unroll
    for (int j = 0; j < 8; j++)
#pragma unroll
        for (int l = 0; l < 4; l++) acc[j][l] = 0.0f;

    if (tid < (KC / 8) * 2)
        csm[tid] = g_c[(k0 / 8 + (tid >> 1)) * C + (n0 >> 4) + (tid & 1)];
    __syncthreads();

    for (int step = 0; step < KC / 16; step++) {
        const int kb = k0 + step * 16;
#pragma unroll
        for (int j = 0; j < 4; j++) {
            int idx4 = tid + j * 128;            // 0..511
            int row = idx4 >> 5, col4 = idx4 & 31;
            *(float4*)&xs[row][col4 * 4] =
                *(const float4*)(g_xT + (size_t)(kb + row) * B + b0 + col4 * 4);
        }
        {
            int row = tid >> 3, col4 = tid & 7;
            float4 w = *(const float4*)(g_Wt + (size_t)(kb + row) * N160 + n0 + col4 * 4);
            float sc = csm[(((step * 16 + row) >> 3) << 1) + (col4 >> 2)];
            w.x *= sc; w.y *= sc; w.z *= sc; w.w *= sc;
            *(float4*)&ws[row][col4 * 4] = w;
        }
        __syncthreads();
#pragma unroll
        for (int kk = 0; kk < 16; kk++) {
            float4 x0 = *(float4*)&xs[kk][tm * 8];
            float4 x1 = *(float4*)&xs[kk][tm * 8 + 4];
            float4 w0 = *(float4*)&ws[kk][tn * 4];
            float xv[8] = {x0.x, x0.y, x0.z, x0.w, x1.x, x1.y, x1.z, x1.w};
            float wv[4] = {w0.x, w0.y, w0.z, w0.w};
#pragma unroll
            for (int j = 0; j < 8; j++)
#pragma unroll
                for (int l = 0; l < 4; l++)
                    acc[j][l] = fmaf(xv[j], wv[l], acc[j][l]);
        }
        __syncthreads();
    }

    float* sp = g_spart + (size_t)blockIdx.z * (B * N160);
#pragma unroll
    for (int j = 0; j < 8; j++)
        *(float4*)&sp[(size_t)(b0 + tm * 8 + j) * N160 + n0 + tn * 4] =
            make_float4(acc[j][0], acc[j][1], acc[j][2], acc[j][3]);
}

// reduce partials + squash. v = s*|s|/(1+s^2). float4-vectorized.
__global__ void squash_k(float* __restrict__ out) {
    const int idx = blockIdx.x * 256 + threadIdx.x;  // < 10240 float4s
    const float4* sp = (const float4*)g_spart;
    float4 s = make_float4(0.f, 0.f, 0.f, 0.f);
#pragma unroll 8
    for (int ks = 0; ks < NKS; ks++) {
        float4 t = sp[(size_t)ks * (B * N160 / 4) + idx];
        s.x += t.x; s.y += t.y; s.z += t.z; s.w += t.w;
    }
    float4 v;
    v.x = s.x * fabsf(s.x) / (1.0f + s.x * s.x);
    v.y = s.y * fabsf(s.y) / (1.0f + s.y * s.y);
    v.z = s.z * fabsf(s.z) / (1.0f + s.z * s.z);
    v.w = s.w * fabsf(s.w) / (1.0f + s.w * s.w);
    ((float4*)g_v)[idx] = v;
    if (out) ((float4*)out)[idx] = v;
}

// Agreement fused: G[m=(r,i)][n=(c,o)] = sum_b x[b][m]*v[b][n], then
// g_bp[z][r,c] = (1/B) * sum_{i,o} G * W[r,c,o,i], batch split over ZS=4.
// as[kk=b][m] loaded DIRECTLY from x (k contiguous). grid (72, 5, ZS).
__global__ void __launch_bounds__(128) gemm2_k(const float* __restrict__ x,
                                               const float* __restrict__ W) {
    const int m0 = blockIdx.x * 128, n0 = blockIdx.y * 32;
    const int zz = blockIdx.z;  // batch quarter
    const int tid = threadIdx.x;
    const int tn = tid & 7, tm = tid >> 3;

    __shared__ float as[16][132];  // [kk=b][m], padded
    __shared__ float vs[16][32];
    float acc[8][4];
#pragma unroll
    for (int j = 0; j < 8; j++)
#pragma unroll
        for (int l = 0; l < 4; l++) acc[j][l] = 0.0f;

    const int arow = tid >> 5, acol4 = tid & 31;  // + j*4 rows

    for (int step = 0; step < B / (16 * ZS); step++) {
        const int bb = zz * (B / ZS) + step * 16;
#pragma unroll
        for (int j = 0; j < 4; j++) {
            int row = arow + j * 4;               // batch row within tile
            *(float4*)&as[row][acol4 * 4] =
                *(const float4*)(x + (size_t)(bb + row) * K9 + m0 + acol4 * 4);
        }
        {
            int row = tid >> 3, col4 = tid & 7;
            *(float4*)&vs[row][col4 * 4] =
                *(const float4*)(g_v + (size_t)(bb + row) * N160 + n0 + col4 * 4);
        }
        __syncthreads();
#pragma unroll
        for (int kk = 0; kk < 16; kk++) {
            float4 x0 = *(float4*)&as[kk][tm * 8];
            float4 x1 = *(float4*)&as[kk][tm * 8 + 4];
            float4 w0 = *(float4*)&vs[kk][tn * 4];
            float xv[8] = {x0.x, x0.y, x0.z, x0.w, x1.x, x1.y, x1.z, x1.w};
            float wv[4] = {w0.x, w0.y, w0.z, w0.w};
#pragma unroll
            for (int j = 0; j < 8; j++)
#pragma unroll
                for (int l = 0; l < 4; l++)
                    acc[j][l] = fmaf(xv[j], wv[l], acc[j][l]);
        }
        __syncthreads();
    }

    // Epilogue: each thread's 8 m span exactly one r (i = 0..7), 4 n within one c.
    const int r = (m0 >> 3) + tm;            // m0 + tm*8 -> r, i=j
    const int nb = n0 + tn * 4;
    const int c = nb >> 4, o0 = nb & 15;
    const float* wrc = W + ((size_t)(r * C + c) * O) * I;
    float part = 0.0f;
#pragma unroll
    for (int j = 0; j < 8; j++)
#pragma unroll
        for (int l = 0; l < 4; l++)
            part = fmaf(acc[j][l], wrc[(o0 + l) * I + j], part);

    __shared__ float red[32][4];
    const int slot = tm * 2 + (tn >> 2);     // (r_local, c_local) -> 0..31
    red[slot][tn & 3] = part;
    __syncthreads();
    if (tid < 32) {
        float s = red[tid][0] + red[tid][1] + red[tid][2] + red[tid][3];
        int rr = (m0 >> 3) + (tid >> 1);
        int cc = (n0 >> 4) + (tid & 1);
        g_bp[zz * (R * C) + rr * C + cc] = s * (1.0f / (float)B);
    }
}

extern "C" void kernel_launch(void* const* d_in, const int* in_sizes, int n_in,
                              void* d_out, int out_size) {
    const float* x = (const float*)d_in[0];
    const float* W = (const float*)d_in[1];
    if (n_in >= 2 && in_sizes[0] == R * C * O * I) {
        x = (const float*)d_in[1];
        W = (const float*)d_in[0];
    }

    prologue_k<<<3501, 256>>>(x, W);

    for (int it = 0; it < 3; it++) {
        if (it > 0) softmax_k<<<C, 128>>>();
        gemm1_k<<<dim3(B / 128, N160 / 32, NKS), 128>>>();
        squash_k<<<(B * N160 / 4) / 256, 256>>>(it == 2 ? (float*)d_out : nullptr);
        if (it < 2) gemm2_k<<<dim3(K9 / 128, N160 / 32, ZS), 128>>>(x, W);
    }
}

// round 16
// speedup vs baseline: 1.2803x; 1.2803x over previous
#include <cuda_runtime.h>

#define B 256
#define R 1152
#define C 10
#define O 16
#define I 8
#define K9 (R * I)      // 9216
#define N160 (C * O)    // 160
#define NKS 64          // K-split for gemm1
#define KC (K9 / NKS)   // 144
#define ZS 2            // gemm2 batch split

__device__ float g_b[R * C];
__device__ float g_bp[ZS * R * C];       // gemm2 batch-split partials
__device__ float g_c[R * C];
__device__ float g_xT[K9 * B];           // xT[k][b]  (gemm1 only)
__device__ float g_Wt[K9 * N160];        // Wt[k=(r,i)][n=(c,o)] = W[r,c,o,i]
__device__ float g_v[B * N160];          // v[b][n]
__device__ float g_spart[NKS * B * N160];

// Fused prologue: [0,2304) transpose x -> g_xT; [2304,3456) rearrange W -> g_Wt;
// [3456,3501) init g_c = 1/R, g_b = 0.
__global__ void __launch_bounds__(256) prologue_k(const float* __restrict__ x,
                                                  const float* __restrict__ W) {
    __shared__ float sbuf[1280];  // transpose needs 32*33=1056, W tile needs 1280
    const int bid = blockIdx.x;
    const int tid = threadIdx.x;

    if (bid < 2304) {                 // transpose: 288 x 8 tiles of 32x32
        const int k0 = (bid % 288) * 32, b0 = (bid / 288) * 32;
        const int tx = tid & 31, ty = tid >> 5;  // 32 x 8
#pragma unroll
        for (int j = 0; j < 32; j += 8)
            sbuf[(ty + j) * 33 + tx] = x[(size_t)(b0 + ty + j) * K9 + k0 + tx];
        __syncthreads();
#pragma unroll
        for (int j = 0; j < 32; j += 8)
            g_xT[(size_t)(k0 + ty + j) * B + b0 + tx] = sbuf[tx * 33 + ty + j];
    } else if (bid < 3456) {          // W rearrange, one route per block
        const int r = bid - 2304;
        for (int idx = tid; idx < 1280; idx += 256)
            sbuf[idx] = W[(size_t)r * 1280 + idx];   // layout (c,o,i)
        __syncthreads();
        for (int idx = tid; idx < 1280; idx += 256) {
            int i = idx / N160, n = idx - i * N160;  // n = c*16+o
            g_Wt[(size_t)(r * 8 + i) * N160 + n] = sbuf[n * I + i];
        }
    } else {                          // init
        int i = (bid - 3456) * 256 + tid;
        if (i < R * C) { g_c[i] = 1.0f / (float)R; g_b[i] = 0.0f; }
    }
}

// softmax over routes per capsule c; folds in the ZS gemm2 partials and
// updates g_b for the next iteration. One block per c.
__global__ void __launch_bounds__(128) softmax_k() {
    const int c = blockIdx.x;
    const int tid = threadIdx.x;
    __shared__ float bsm[R];
    __shared__ float red[128];

    for (int r = tid; r < R; r += 128) {
        float t = g_b[r * C + c];
#pragma unroll
        for (int z = 0; z < ZS; z++) t += g_bp[z * (R * C) + r * C + c];
        bsm[r] = t;
    }
    __syncthreads();

    float m = -1e30f;
    for (int r = tid; r < R; r += 128) m = fmaxf(m, bsm[r]);
    red[tid] = m;
    __syncthreads();
    for (int s = 64; s > 0; s >>= 1) {
        if (tid < s) red[tid] = fmaxf(red[tid], red[tid + s]);
        __syncthreads();
    }
    m = red[0];
    __syncthreads();

    float sum = 0.0f;
    for (int r = tid; r < R; r += 128) sum += expf(bsm[r] - m);
    red[tid] = sum;
    __syncthreads();
    for (int s = 64; s > 0; s >>= 1) {
        if (tid < s) red[tid] += red[tid + s];
        __syncthreads();
    }
    float inv = 1.0f / red[0];

    for (int r = tid; r < R; r += 128) {
        g_b[r * C + c] = bsm[r];
        g_c[r * C + c] = expf(bsm[r] - m) * inv;
    }
}

// GEMM1 partials: spart[ks][b][n] = sum_{k in chunk} xT[k][b] * (c[r(k),cap(n)] * Wt[k][n])
// tile 128(b) x 32(n), 128 threads, 8x4/thread, single-buffered.
// c_ij scale folded via smem csm (no scattered LDG). grid (2, 5, NKS).
__global__ void __launch_bounds__(128) gemm1_k() {
    const int b0 = blockIdx.x * 128, n0 = blockIdx.y * 32;
    const int k0 = blockIdx.z * KC;
    const int tid = threadIdx.x;
    const int tn = tid & 7, tm = tid >> 3;  // tn 0..7 (n), tm 0..15 (b)

    __shared__ float xs[16][128];
    __shared__ float ws[16][32];
    __shared__ float csm[(KC / 8) * 2];     // 18 routes x 2 caps
    float acc[8][4];
#pragma unroll
    for (int j = 0; j < 8; j++)
#pragma unroll
        for (int l = 0; l < 4; l++) acc[j][l] = 0.0f;

    if (tid < (KC / 8) * 2)
        csm[tid] = g_c[(k0 / 8 + (tid >> 1)) * C + (n0 >> 4) + (tid & 1)];
    __syncthreads();

    for (int step = 0; step < KC / 16; step++) {
        const int kb = k0 + step * 16;
#pragma unroll
        for (int j = 0; j < 4; j++) {
            int idx4 = tid + j * 128;            // 0..511
            int row = idx4 >> 5, col4 = idx4 & 31;
            *(float4*)&xs[row][col4 * 4] =
                *(const float4*)(g_xT + (size_t)(kb + row) * B + b0 + col4 * 4);
        }
        {
            int row = tid >> 3, col4 = tid & 7;
            float4 w = *(const float4*)(g_Wt + (size_t)(kb + row) * N160 + n0 + col4 * 4);
            float sc = csm[(((step * 16 + row) >> 3) << 1) + (col4 >> 2)];
            w.x *= sc; w.y *= sc; w.z *= sc; w.w *= sc;
            *(float4*)&ws[row][col4 * 4] = w;
        }
        __syncthreads();
#pragma unroll
        for (int kk = 0; kk < 16; kk++) {
            float4 x0 = *(float4*)&xs[kk][tm * 8];
            float4 x1 = *(float4*)&xs[kk][tm * 8 + 4];
            float4 w0 = *(float4*)&ws[kk][tn * 4];
            float xv[8] = {x0.x, x0.y, x0.z, x0.w, x1.x, x1.y, x1.z, x1.w};
            float wv[4] = {w0.x, w0.y, w0.z, w0.w};
#pragma unroll
            for (int j = 0; j < 8; j++)
#pragma unroll
                for (int l = 0; l < 4; l++)
                    acc[j][l] = fmaf(xv[j], wv[l], acc[j][l]);
        }
        __syncthreads();
    }

    float* sp = g_spart + (size_t)blockIdx.z * (B * N160);
#pragma unroll
    for (int j = 0; j < 8; j++)
        *(float4*)&sp[(size_t)(b0 + tm * 8 + j) * N160 + n0 + tn * 4] =
            make_float4(acc[j][0], acc[j][1], acc[j][2], acc[j][3]);
}

// reduce partials + squash. v = s*|s|/(1+s^2). float4-vectorized.
__global__ void squash_k(float* __restrict__ out) {
    const int idx = blockIdx.x * 256 + threadIdx.x;  // < 10240 float4s
    const float4* sp = (const float4*)g_spart;
    float4 s = make_float4(0.f, 0.f, 0.f, 0.f);
#pragma unroll 8
    for (int ks = 0; ks < NKS; ks++) {
        float4 t = sp[(size_t)ks * (B * N160 / 4) + idx];
        s.x += t.x; s.y += t.y; s.z += t.z; s.w += t.w;
    }
    float4 v;
    v.x = s.x * fabsf(s.x) / (1.0f + s.x * s.x);
    v.y = s.y * fabsf(s.y) / (1.0f + s.y * s.y);
    v.z = s.z * fabsf(s.z) / (1.0f + s.z * s.z);
    v.w = s.w * fabsf(s.w) / (1.0f + s.w * s.w);
    ((float4*)g_v)[idx] = v;
    if (out) ((float4*)out)[idx] = v;
}

// Agreement fused: G[m=(r,i)][n=(c,o)] = sum_b x[b][m]*v[b][n], then
// g_bp[z][r,c] = (1/B) * sum_{i,o} G * W[r,c,o,i], batch split over ZS=2.
// Epilogue reads weights from g_Wt (coalesced float4), NOT raw W.
// tile 128(m) x 32(n), 128 threads, 8x4 per thread. grid (72, 5, ZS).
__global__ void __launch_bounds__(128) gemm2_k(const float* __restrict__ x) {
    const int m0 = blockIdx.x * 128, n0 = blockIdx.y * 32;
    const int zz = blockIdx.z;  // batch half
    const int tid = threadIdx.x;
    const int tn = tid & 7, tm = tid >> 3;

    __shared__ float as[16][132];  // [kk=b][m], padded
    __shared__ float vs[16][32];
    float acc[8][4];
#pragma unroll
    for (int j = 0; j < 8; j++)
#pragma unroll
        for (int l = 0; l < 4; l++) acc[j][l] = 0.0f;

    const int arow = tid >> 5, acol4 = tid & 31;  // + j*4 rows

    for (int step = 0; step < B / (16 * ZS); step++) {
        const int bb = zz * (B / ZS) + step * 16;
#pragma unroll
        for (int j = 0; j < 4; j++) {
            int row = arow + j * 4;               // batch row within tile
            *(float4*)&as[row][acol4 * 4] =
                *(const float4*)(x + (size_t)(bb + row) * K9 + m0 + acol4 * 4);
        }
        {
            int row = tid >> 3, col4 = tid & 7;
            *(float4*)&vs[row][col4 * 4] =
                *(const float4*)(g_v + (size_t)(bb + row) * N160 + n0 + col4 * 4);
        }
        __syncthreads();
#pragma unroll
        for (int kk = 0; kk < 16; kk++) {
            float4 x0 = *(float4*)&as[kk][tm * 8];
            float4 x1 = *(float4*)&as[kk][tm * 8 + 4];
            float4 w0 = *(float4*)&vs[kk][tn * 4];
            float xv[8] = {x0.x, x0.y, x0.z, x0.w, x1.x, x1.y, x1.z, x1.w};
            float wv[4] = {w0.x, w0.y, w0.z, w0.w};
#pragma unroll
            for (int j = 0; j < 8; j++)
#pragma unroll
                for (int l = 0; l < 4; l++)
                    acc[j][l] = fmaf(xv[j], wv[l], acc[j][l]);
        }
        __syncthreads();
    }

    // Epilogue: thread's 8 m-rows are k = m0+tm*8+j (one route r, i=j); its 4 n
    // are contiguous. Weights come from g_Wt[k][n] as 8 coalesced float4 loads.
    const int nb = n0 + tn * 4;
    float part = 0.0f;
#pragma unroll
    for (int j = 0; j < 8; j++) {
        float4 w4 = *(const float4*)(g_Wt + (size_t)(m0 + tm * 8 + j) * N160 + nb);
        part = fmaf(acc[j][0], w4.x, part);
        part = fmaf(acc[j][1], w4.y, part);
        part = fmaf(acc[j][2], w4.z, part);
        part = fmaf(acc[j][3], w4.w, part);
    }

    __shared__ float red[32][4];
    const int slot = tm * 2 + (tn >> 2);     // (r_local, c_local) -> 0..31
    red[slot][tn & 3] = part;
    __syncthreads();
    if (tid < 32) {
        float s = red[tid][0] + red[tid][1] + red[tid][2] + red[tid][3];
        int rr = (m0 >> 3) + (tid >> 1);
        int cc = (n0 >> 4) + (tid & 1);
        g_bp[zz * (R * C) + rr * C + cc] = s * (1.0f / (float)B);
    }
}

extern "C" void kernel_launch(void* const* d_in, const int* in_sizes, int n_in,
                              void* d_out, int out_size) {
    const float* x = (const float*)d_in[0];
    const float* W = (const float*)d_in[1];
    if (n_in >= 2 && in_sizes[0] == R * C * O * I) {
        x = (const float*)d_in[1];
        W = (const float*)d_in[0];
    }

    prologue_k<<<3501, 256>>>(x, W);

    for (int it = 0; it < 3; it++) {
        if (it > 0) softmax_k<<<C, 128>>>();
        gemm1_k<<<dim3(B / 128, N160 / 32, NKS), 128>>>();
        squash_k<<<(B * N160 / 4) / 256, 256>>>(it == 2 ? (float*)d_out : nullptr);
        if (it < 2) gemm2_k<<<dim3(K9 / 128, N160 / 32, ZS), 128>>>(x);
    }
}